// round 13
// baseline (speedup 1.0000x reference)
#include <cuda_runtime.h>
#include <cstdint>

// OptimizedSeriesDecomp: x[32,4096,512] fp32
//   trend = mean_{k in {7,25,49}} boxfilter_k(x, replicate pad) along L
//   out   = concat(residual = x - trend, trend)
//
// R13 == R12 (never benched: GPU acquisition failure). Warp-specialized
// drain. R11 measured DRAM=77% with 2 __syncthreads per body (~13% straggle
// tax, matching the gap to the ~112us BW floor). Now: 16 compute warps (512
// thr) run the register delay line (BATCH=8, HIST=57) with NO block barriers;
// they STS 8-row tiles into a 4-deep smem ring and signal per-warp via
// mbarrier. One drain thread (warp 16) owns ALL cp.async.bulk state: waits
// full, issues 2x16KB bulk S2G, commits, wait_group.read 3, arrives empty.
// Warps decouple; latency hiding restored.

#define BB     32
#define LL     4096
#define CC     512
#define NCW    512                    // compute threads
#define TPB    544                    // + 1 drain warp
#define BATCH  8
#define HIST   (49 + BATCH)           // 57
#define NBLOCK 148
#define UPS    (LL / BATCH)           // 512 units per strip
#define TOTAL_UNITS (BB * UPS)        // 16384
#define TILE   (BATCH * CC)           // 4096 floats = 16KB per stream tile
#define NBUF   4
#define SMEM_BYTES (NBUF * 2 * TILE * 4)   // 128KB

__device__ __forceinline__ uint32_t smem_u32(const void* p) {
    uint32_t a;
    asm("{ .reg .u64 t; cvta.to.shared.u64 t, %1; cvt.u32.u64 %0, t; }"
        : "=r"(a) : "l"(p));
    return a;
}
__device__ __forceinline__ void bulk_s2g(void* g, uint32_t s, uint32_t nbytes) {
    asm volatile("cp.async.bulk.global.shared::cta.bulk_group [%0], [%1], %2;"
                 :: "l"(g), "r"(s), "r"(nbytes) : "memory");
}
__device__ __forceinline__ void mbar_init(uint32_t m, uint32_t cnt) {
    asm volatile("mbarrier.init.shared.b64 [%0], %1;" :: "r"(m), "r"(cnt) : "memory");
}
__device__ __forceinline__ void mbar_arrive(uint32_t m) {
    asm volatile("mbarrier.arrive.shared::cta.b64 _, [%0];" :: "r"(m) : "memory");
}
__device__ __forceinline__ void mbar_wait(uint32_t m, uint32_t parity) {
    asm volatile(
        "{\n\t.reg .pred P;\n\t"
        "W_%=:\n\t"
        "mbarrier.try_wait.parity.acquire.cta.shared::cta.b64 P, [%0], %1, 0x989680;\n\t"
        "@P bra.uni D_%=;\n\t"
        "bra.uni W_%=;\n\t"
        "D_%=:\n\t}"
        :: "r"(m), "r"(parity) : "memory");
}

__global__ __launch_bounds__(TPB, 1)
void series_decomp_kernel(const float* __restrict__ x,
                          float* __restrict__ out,
                          long long nhalf)
{
    extern __shared__ float stage[];           // [NBUF][2][TILE]
    __shared__ uint64_t mbar[2 * NBUF];        // full[0..3], empty[0..3]
    const int tid = threadIdx.x;
    const uint32_t stage_base = smem_u32(stage);
    const uint32_t mb0 = smem_u32(&mbar[0]);   // full[i]  at mb0 + 8*i
    const uint32_t mbE = mb0 + 8 * NBUF;       // empty[i] at mbE + 8*i

    if (tid == 0) {
        #pragma unroll
        for (int i = 0; i < NBUF; ++i) {
            mbar_init(mb0 + 8 * i, 16);        // full: one arrive per compute warp
            mbar_init(mbE + 8 * i, 1);         // empty: drain thread
        }
    }
    __syncthreads();

    int u0 = (int)(((long long)blockIdx.x       * TOTAL_UNITS) / NBLOCK);
    int u1 = (int)(((long long)(blockIdx.x + 1) * TOTAL_UNITS) / NBLOCK);

    if (tid < NCW) {
        // ================= compute warps =================
        const int lane = tid & 31;
        const float w7  = 1.0f / (7.0f  * 3.0f);
        const float w25 = 1.0f / (25.0f * 3.0f);
        const float w49 = 1.0f / (49.0f * 3.0f);
        int k = 0;   // global body counter (ring position)

        while (u0 < u1) {
            const int b    = u0 / UPS;
            const int su   = u0 % UPS;
            const int len  = min(UPS - su, u1 - u0);
            const int t0   = su * BATCH;
            const int tend = t0 + len * BATCH;

            const float* __restrict__ xp = x + (size_t)b * (LL * CC) + tid;

            // warmup: h[j] = x[clamp(t0 - 24 + j)], j = 0..56
            float h[HIST];
            #pragma unroll
            for (int j = 0; j < HIST; ++j) {
                int t = t0 - 24 + j;
                t = t < 0 ? 0 : (t > LL - 1 ? LL - 1 : t);
                h[j] = __ldg(xp + (size_t)t * CC);
            }
            float s7 = 0.f, s25 = 0.f, s49 = 0.f;
            #pragma unroll
            for (int j = 0;  j < 49; ++j) s49 += h[j];
            #pragma unroll
            for (int j = 12; j < 37; ++j) s25 += h[j];
            #pragma unroll
            for (int j = 21; j < 28; ++j) s7  += h[j];

            // first prefetch: rows t0+33 .. t0+40 (consumed by body t0's shift)
            float nxt[BATCH];
            #pragma unroll
            for (int j = 0; j < BATCH; ++j) {
                int t = t0 + 33 + j;
                t = t > LL - 1 ? LL - 1 : t;
                nxt[j] = __ldg(xp + (size_t)t * CC);
            }

            #pragma unroll 1
            for (int tb = t0; tb < tend; tb += BATCH) {
                const int buf = k & (NBUF - 1);
                mbar_wait(mbE + 8 * buf, (k >> 2) & 1);   // buffer drained?

                float* __restrict__ sr = stage + (buf * 2 + 0) * TILE;
                float* __restrict__ st = stage + (buf * 2 + 1) * TILE;
                #pragma unroll
                for (int i = 0; i < BATCH; ++i) {
                    float tr = s7 * w7 + s25 * w25 + s49 * w49;
                    float xc = h[24 + i];
                    sr[i * CC + tid] = xc - tr;
                    st[i * CC + tid] = tr;
                    s7  += h[28 + i] - h[21 + i];
                    s25 += h[37 + i] - h[12 + i];
                    s49 += h[49 + i] - h[i];
                }
                asm volatile("fence.proxy.async.shared::cta;" ::: "memory");
                __syncwarp();
                if (lane == 0) mbar_arrive(mb0 + 8 * buf);

                // shift (consumes nxt loaded one body ago), then prefetch
                #pragma unroll
                for (int j = 0; j < HIST - BATCH; ++j) h[j] = h[j + BATCH];
                #pragma unroll
                for (int j = 0; j < BATCH; ++j) h[HIST - BATCH + j] = nxt[j];
                #pragma unroll
                for (int j = 0; j < BATCH; ++j) {
                    int t = tb + 41 + j;                  // rows for next shift
                    t = t > LL - 1 ? LL - 1 : t;
                    nxt[j] = __ldg(xp + (size_t)t * CC);
                }
                ++k;
            }
            u0 += len;
        }
    } else if (tid == NCW) {
        // ================= drain thread =================
        // pre-arm all empty barriers (completes phase 0 of each)
        #pragma unroll
        for (int i = 0; i < NBUF; ++i) mbar_arrive(mbE + 8 * i);

        int k = 0;
        while (u0 < u1) {
            const int b   = u0 / UPS;
            const int su  = u0 % UPS;
            const int len = min(UPS - su, u1 - u0);

            for (int un = 0; un < len; ++un) {
                const int tb  = (su + un) * BATCH;
                const int buf = k & (NBUF - 1);
                mbar_wait(mb0 + 8 * buf, (k >> 2) & 1);   // tile ready

                size_t o = ((size_t)b * LL + tb) * CC;
                bulk_s2g(out + o,
                         stage_base + (uint32_t)((buf * 2 + 0) * TILE * 4),
                         (uint32_t)(TILE * 4));
                bulk_s2g(out + nhalf + o,
                         stage_base + (uint32_t)((buf * 2 + 1) * TILE * 4),
                         (uint32_t)(TILE * 4));
                asm volatile("cp.async.bulk.commit_group;" ::: "memory");
                asm volatile("cp.async.bulk.wait_group.read %0;" :: "n"(NBUF - 1) : "memory");
                if (k >= NBUF - 1)
                    mbar_arrive(mbE + 8 * ((k - (NBUF - 1)) & (NBUF - 1)));
                ++k;
            }
            u0 += len;
        }
        asm volatile("cp.async.bulk.wait_group.read 0;" ::: "memory");
    }
    // keep smem alive until all TMA reads have completed (drain thread holds)
    __syncthreads();
}

extern "C" void kernel_launch(void* const* d_in, const int* in_sizes, int n_in,
                              void* d_out, int out_size)
{
    const float* x = (const float*)d_in[0];
    float* out = (float*)d_out;
    long long nhalf = (long long)out_size / 2;   // residual | trend

    cudaFuncSetAttribute(series_decomp_kernel,
                         cudaFuncAttributeMaxDynamicSharedMemorySize, SMEM_BYTES);
    series_decomp_kernel<<<NBLOCK, TPB, SMEM_BYTES>>>(x, out, nhalf);
}